// round 13
// baseline (speedup 1.0000x reference)
#include <cuda_runtime.h>
#include <cuda_fp16.h>
#include <cstdint>

// Problem constants: F=50000, K=32, E=128, N_NODE=100000
#define KNBR 32
#define EMB  128
#define MAXF 50000
#define MAXN 100000

// Scratch (no cudaMalloc allowed)
__device__ float g_p[MAXN];                                // 0.4 MB
__device__ alignas(16) __half g_emb_h [MAXN * EMB];        // 25.6 MB
__device__ alignas(16) __half g_embf_h[MAXF * EMB];        // 12.8 MB
__device__ alignas(16) __half g_aggh  [MAXF * EMB];        // 12.8 MB
__device__ unsigned g_tile_ready[1024];                    // per-tile producer count

// ---------------------------------------------------------------------------
// PTX helpers
// ---------------------------------------------------------------------------
__device__ __forceinline__ void ldsm_x4(uint32_t& r0, uint32_t& r1,
                                        uint32_t& r2, uint32_t& r3, uint32_t a)
{
    asm volatile("ldmatrix.sync.aligned.m8n8.x4.shared.b16 {%0,%1,%2,%3}, [%4];"
                 : "=r"(r0), "=r"(r1), "=r"(r2), "=r"(r3) : "r"(a));
}
__device__ __forceinline__ void mma16816(float* d, const uint32_t* a,
                                         uint32_t b0, uint32_t b1)
{
    asm volatile(
        "mma.sync.aligned.m16n8k16.row.col.f32.f16.f16.f32 "
        "{%0,%1,%2,%3}, {%4,%5,%6,%7}, {%8,%9}, {%0,%1,%2,%3};"
        : "+f"(d[0]), "+f"(d[1]), "+f"(d[2]), "+f"(d[3])
        : "r"(a[0]), "r"(a[1]), "r"(a[2]), "r"(a[3]), "r"(b0), "r"(b1));
}
__device__ __forceinline__ void cp_async16(uint32_t saddr, const void* gaddr)
{
    asm volatile("cp.async.cg.shared.global [%0], [%1], 16;"
                 :: "r"(saddr), "l"(gaddr));
}

// ---------------------------------------------------------------------------
// Kernel PRE: p[n] = dot(emb_i[n], u) + fp16 copy of emb_i (2 nodes/warp).
// Block 0 additionally zeroes the tile-ready counters (replay-safe).
// ---------------------------------------------------------------------------
__global__ __launch_bounds__(256) void pre_kernel(
    const float* __restrict__ emb_i, const float* __restrict__ u, int N)
{
    if (blockIdx.x == 0) {
#pragma unroll
        for (int i = threadIdx.x; i < 1024; i += 256) g_tile_ready[i] = 0u;
    }

    const int wid  = threadIdx.x >> 5;
    const int lane = threadIdx.x & 31;
    const int n0 = (blockIdx.x * 8 + wid) * 2;
    if (n0 >= N) return;
    const int n1 = n0 + 1;
    const bool has1 = (n1 < N);

    float4 uu = *reinterpret_cast<const float4*>(u + lane * 4);
    float4 v0 = *reinterpret_cast<const float4*>(emb_i + (size_t)n0 * EMB + lane * 4);
    float4 v1 = has1
        ? *reinterpret_cast<const float4*>(emb_i + (size_t)n1 * EMB + lane * 4)
        : make_float4(0.f, 0.f, 0.f, 0.f);

    {
        __half2 a0 = __float22half2_rn(make_float2(v0.x, v0.y));
        __half2 a1 = __float22half2_rn(make_float2(v0.z, v0.w));
        uint2 hw;
        hw.x = *reinterpret_cast<uint32_t*>(&a0);
        hw.y = *reinterpret_cast<uint32_t*>(&a1);
        *reinterpret_cast<uint2*>(&g_emb_h[(size_t)n0 * EMB + lane * 4]) = hw;
    }
    if (has1) {
        __half2 a0 = __float22half2_rn(make_float2(v1.x, v1.y));
        __half2 a1 = __float22half2_rn(make_float2(v1.z, v1.w));
        uint2 hw;
        hw.x = *reinterpret_cast<uint32_t*>(&a0);
        hw.y = *reinterpret_cast<uint32_t*>(&a1);
        *reinterpret_cast<uint2*>(&g_emb_h[(size_t)n1 * EMB + lane * 4]) = hw;
    }

    float s0 = v0.x * uu.x + v0.y * uu.y + v0.z * uu.z + v0.w * uu.w;
    float s1 = v1.x * uu.x + v1.y * uu.y + v1.z * uu.z + v1.w * uu.w;
#pragma unroll
    for (int off = 16; off > 0; off >>= 1) {
        s0 += __shfl_xor_sync(0xffffffffu, s0, off);
        s1 += __shfl_xor_sync(0xffffffffu, s1, off);
    }
    if (lane == 0) {
        g_p[n0] = s0;
        if (has1) g_p[n1] = s1;
    }
}

// ---------------------------------------------------------------------------
// MAIN kernel: interleaved producers + consumers, 25-block groups.
//  bid = 25g + r.  r<24: producer p = 24g+r (8 features: softmax+gather ->
//  aggh, embf fp32->fp16), signals g_tile_ready[p>>3].
//  r==24: consumer g (gate tiles 3g..3g+2): spin-wait tile, cp.async cat,
//  HMMA K=256, sigmoid-gate epilogue. Consumers trail their producers in
//  dispatch order -> readiness & no deadlock.
// ---------------------------------------------------------------------------
#define TM 64
#define WK_LD   264                      // halves per n-row (256 + 8 pad)
#define CAT_LDH 264                      // halves per f-row (256 + 8 pad)
#define S_W_HALFS    (128 * WK_LD)       // 67584 B
#define S_CAT_HALFS  (TM * CAT_LDH)      // 33792 B
#define SMEM_MAIN_B  ((S_W_HALFS + S_CAT_HALFS) * 2)     // 101376 B

__global__ __launch_bounds__(256, 2) void main_kernel(
    const int* __restrict__ adj,      // [F, 32]
    const float* __restrict__ emb_f,  // [F, 128] fp32
    const float* __restrict__ W,      // [128, 256] row-major (n=e, k=j)
    const float* __restrict__ bias,   // [128]
    float* __restrict__ out,          // [F, 128]
    int F)
{
    extern __shared__ __half hsmem[];
    const int g    = blockIdx.x / 25;
    const int role = blockIdx.x % 25;
    const int nprod  = (F + 7) / 8;
    const int ntiles = (F + TM - 1) / TM;
    const int t    = threadIdx.x;
    const int lane = t & 31;
    const int wid  = t >> 5;

    if (role < 24) {
        // ================= PRODUCER =================
        const int p = g * 24 + role;
        if (p >= nprod) return;
        const int f = p * 8 + wid;

        if (f < F) {
            // softmax over neighbors (lane k owns neighbor k)
            int   idx = adj[(size_t)f * KNBR + lane];
            float a = g_p[idx] + (idx != 0 ? 0.0f : -10000.0f);
            float m = a;
#pragma unroll
            for (int off = 16; off > 0; off >>= 1)
                m = fmaxf(m, __shfl_xor_sync(0xffffffffu, m, off));
            float e = __expf(a - m);
            float sum = e;
#pragma unroll
            for (int off = 16; off > 0; off >>= 1)
                sum += __shfl_xor_sync(0xffffffffu, sum, off);
            float al = e / sum;

            const int half = lane >> 4;
            const int li   = lane & 15;
            const uint4* base = reinterpret_cast<const uint4*>(g_emb_h);
            float acc[8];
#pragma unroll
            for (int j = 0; j < 8; j++) acc[j] = 0.0f;

#pragma unroll 8
            for (int ki = 0; ki < KNBR / 2; ki++) {
                int src  = 2 * ki + half;
                int row  = __shfl_sync(0xffffffffu, idx, src);
                float ak = __shfl_sync(0xffffffffu, al,  src);
                uint4 hv = __ldg(base + (size_t)((unsigned)row) * (EMB / 8) + li);
                float2 v0 = __half22float2(*reinterpret_cast<__half2*>(&hv.x));
                float2 v1 = __half22float2(*reinterpret_cast<__half2*>(&hv.y));
                float2 v2 = __half22float2(*reinterpret_cast<__half2*>(&hv.z));
                float2 v3 = __half22float2(*reinterpret_cast<__half2*>(&hv.w));
                acc[0] = fmaf(ak, v0.x, acc[0]);
                acc[1] = fmaf(ak, v0.y, acc[1]);
                acc[2] = fmaf(ak, v1.x, acc[2]);
                acc[3] = fmaf(ak, v1.y, acc[3]);
                acc[4] = fmaf(ak, v2.x, acc[4]);
                acc[5] = fmaf(ak, v2.y, acc[5]);
                acc[6] = fmaf(ak, v3.x, acc[6]);
                acc[7] = fmaf(ak, v3.y, acc[7]);
            }
#pragma unroll
            for (int j = 0; j < 8; j++)
                acc[j] += __shfl_xor_sync(0xffffffffu, acc[j], 16);

            if (half == 0) {
                __half2 o0 = __float22half2_rn(make_float2(acc[0], acc[1]));
                __half2 o1 = __float22half2_rn(make_float2(acc[2], acc[3]));
                __half2 o2 = __float22half2_rn(make_float2(acc[4], acc[5]));
                __half2 o3 = __float22half2_rn(make_float2(acc[6], acc[7]));
                uint4 ow;
                ow.x = *reinterpret_cast<uint32_t*>(&o0);
                ow.y = *reinterpret_cast<uint32_t*>(&o1);
                ow.z = *reinterpret_cast<uint32_t*>(&o2);
                ow.w = *reinterpret_cast<uint32_t*>(&o3);
                *reinterpret_cast<uint4*>(&g_aggh[(size_t)f * EMB + li * 8]) = ow;
            }

            // emb_f fp32 -> fp16 for this feature (lane: 4 floats)
            float4 v = *reinterpret_cast<const float4*>(
                emb_f + (size_t)f * EMB + lane * 4);
            __half2 h0 = __float22half2_rn(make_float2(v.x, v.y));
            __half2 h1 = __float22half2_rn(make_float2(v.z, v.w));
            uint2 hw;
            hw.x = *reinterpret_cast<uint32_t*>(&h0);
            hw.y = *reinterpret_cast<uint32_t*>(&h1);
            *reinterpret_cast<uint2*>(&g_embf_h[(size_t)f * EMB + lane * 4]) = hw;
        }

        __syncthreads();
        __threadfence();
        if (t == 0) atomicAdd(&g_tile_ready[p >> 3], 1u);
        return;
    }

    // ================= CONSUMER (gate tiles 3g..3g+2) =================
    __half* s_w   = hsmem;                 // [n=0..127][k=0..255] (+pad)
    __half* s_cat = hsmem + S_W_HALFS;     // [f=0..63][k=0..255] (+pad)

    const int f0 = (wid >> 1) * 16;
    const int nb = (wid & 1) * 64;

    const uint32_t s_cat_u = (uint32_t)__cvta_generic_to_shared(s_cat);
    const uint32_t s_w_u   = (uint32_t)__cvta_generic_to_shared(s_w);

    // W -> fp16 smem [n][k], direct vectorized copy (once per block)
#pragma unroll
    for (int r = 0; r < 32; r++) {
        int id = t + 256 * r;
        int n  = id >> 6;
        int kq = id & 63;
        float4 v = *reinterpret_cast<const float4*>(W + n * 256 + kq * 4);
        __half2 h0 = __float22half2_rn(make_float2(v.x, v.y));
        __half2 h1 = __float22half2_rn(make_float2(v.z, v.w));
        uint2 hw;
        hw.x = *reinterpret_cast<uint32_t*>(&h0);
        hw.y = *reinterpret_cast<uint32_t*>(&h1);
        *reinterpret_cast<uint2*>(&s_w[n * WK_LD + kq * 4]) = hw;
    }

    const uint32_t a_lane_addr = s_cat_u +
        (uint32_t)(((f0 + (lane & 15)) * CAT_LDH + (lane >> 4) * 8) * 2);
    const uint32_t b_lane_addr = s_w_u +
        (uint32_t)((((nb + (lane >> 4) * 8 + (lane & 7)) * WK_LD)
                    + ((lane >> 3) & 1) * 8) * 2);

#pragma unroll 1
    for (int ti = 0; ti < 3; ti++) {
        const int tile = 3 * g + ti;
        if (tile >= ntiles) break;
        const int fbase = tile * TM;

        __syncthreads();   // prior epilogue done with s_cat (iter 0: W store done)

        // spin-wait for this tile's producers
        if (t == 0) {
            int hi = 8 * tile + 8; if (hi > nprod) hi = nprod;
            unsigned target = (unsigned)(hi - 8 * tile);
            while (atomicAdd(&g_tile_ready[tile], 0u) < target)
                __nanosleep(128);
        }
        __syncthreads();

        // full cat tile via cp.async (L2 path; producers' STGs are visible)
#pragma unroll
        for (int r = 0; r < 8; r++) {
            int id  = t + 256 * r;
            int row = id >> 5;
            int c   = id & 31;
            int gf  = fbase + row; if (gf >= F) gf = F - 1;
            const __half* src = (c < 16)
                ? (g_embf_h + (size_t)gf * EMB + c * 8)
                : (g_aggh   + (size_t)gf * EMB + (c - 16) * 8);
            cp_async16(s_cat_u + (uint32_t)((row * CAT_LDH + c * 8) * 2), src);
        }
        asm volatile("cp.async.commit_group;");
        asm volatile("cp.async.wait_group 0;" ::: "memory");
        __syncthreads();

        // MMA mainloop over K=256
        float acc[32];
#pragma unroll
        for (int i = 0; i < 32; i++) acc[i] = 0.0f;

#pragma unroll
        for (int ks = 0; ks < 16; ks++) {
            const int k0 = ks * 16;
            uint32_t a[4];
            ldsm_x4(a[0], a[1], a[2], a[3], a_lane_addr + (uint32_t)(k0 * 2));
#pragma unroll
            for (int np = 0; np < 4; np++) {
                uint32_t b0, b1, b2, b3;
                ldsm_x4(b0, b1, b2, b3,
                        b_lane_addr + (uint32_t)((np * 16 * WK_LD + k0) * 2));
                mma16816(&acc[(np * 2 + 0) * 4], a, b0, b1);
                mma16816(&acc[(np * 2 + 1) * 4], a, b2, b3);
            }
        }

        // Epilogue: ef/agg fp16 from s_cat
        const int r  = lane >> 2;
        const int cq = (lane & 3) * 2;
#pragma unroll
        for (int tj = 0; tj < 8; tj++) {
            int c = nb + tj * 8 + cq;
            float2 b2v = *reinterpret_cast<const float2*>(bias + c);
#pragma unroll
            for (int h = 0; h < 2; h++) {
                int frow = f0 + r + 8 * h;
                int f = fbase + frow;
                if (f >= F) continue;
                float x0 = acc[tj * 4 + 2 * h]     + b2v.x;
                float x1 = acc[tj * 4 + 2 * h + 1] + b2v.y;
                float g0 = 1.0f / (1.0f + __expf(-x0));
                float g1 = 1.0f / (1.0f + __expf(-x1));
                float2 ef = __half22float2(
                    *reinterpret_cast<const __half2*>(&s_cat[frow * CAT_LDH + c]));
                float2 ag = __half22float2(
                    *reinterpret_cast<const __half2*>(&s_cat[frow * CAT_LDH + 128 + c]));
                float2 o;
                o.x = g0 * ef.x + (1.0f - g0) * ag.x;
                o.y = g1 * ef.y + (1.0f - g1) * ag.y;
                *reinterpret_cast<float2*>(out + (size_t)f * EMB + c) = o;
            }
        }
    }
}

// ---------------------------------------------------------------------------
extern "C" void kernel_launch(void* const* d_in, const int* in_sizes, int n_in,
                              void* d_out, int out_size)
{
    const int*   adj   = (const int*)d_in[0];     // [F,32]
    const float* emb_i = (const float*)d_in[1];   // [N,128]
    const float* emb_f = (const float*)d_in[2];   // [F,128]
    const float* u     = (const float*)d_in[3];   // [128]
    const float* W     = (const float*)d_in[4];   // [128,256]
    const float* bias  = (const float*)d_in[5];   // [128]
    float*       out   = (float*)d_out;           // [F,128]

    const int F = in_sizes[0] / KNBR;
    const int N = in_sizes[1] / EMB;

    cudaFuncSetAttribute(main_kernel,
                         cudaFuncAttributeMaxDynamicSharedMemorySize, SMEM_MAIN_B);

    // pre: 16 nodes per block (2 per warp); block 0 zeroes tile counters
    int nblk_pre = (((N + 1) / 2) + 7) / 8;
    pre_kernel<<<nblk_pre, 256>>>(emb_i, u, N);

    // main: interleaved producer/consumer groups of 25 blocks
    int ntiles  = (F + TM - 1) / TM;
    int ngroups = (ntiles + 2) / 3;
    main_kernel<<<ngroups * 25, 256, SMEM_MAIN_B>>>(adj, emb_f, W, bias, out, F);
}

// round 14
// speedup vs baseline: 1.9429x; 1.9429x over previous
#include <cuda_runtime.h>
#include <cuda_fp16.h>
#include <cstdint>

// Problem constants: F=50000, K=32, E=128, N_NODE=100000
#define KNBR 32
#define EMB  128
#define MAXF 50000
#define MAXN 100000

// Scratch (no cudaMalloc allowed)
__device__ float g_p[MAXN];                                // 0.4 MB
__device__ alignas(16) __half g_emb_h [MAXN * EMB];        // 25.6 MB
__device__ alignas(16) __half g_embf_h[MAXF * EMB];        // 12.8 MB
__device__ alignas(16) __half g_aggh  [MAXF * EMB];        // 12.8 MB

// ---------------------------------------------------------------------------
// PTX helpers
// ---------------------------------------------------------------------------
__device__ __forceinline__ void ldsm_x4(uint32_t& r0, uint32_t& r1,
                                        uint32_t& r2, uint32_t& r3, uint32_t a)
{
    asm volatile("ldmatrix.sync.aligned.m8n8.x4.shared.b16 {%0,%1,%2,%3}, [%4];"
                 : "=r"(r0), "=r"(r1), "=r"(r2), "=r"(r3) : "r"(a));
}
__device__ __forceinline__ void mma16816(float* d, const uint32_t* a,
                                         uint32_t b0, uint32_t b1)
{
    asm volatile(
        "mma.sync.aligned.m16n8k16.row.col.f32.f16.f16.f32 "
        "{%0,%1,%2,%3}, {%4,%5,%6,%7}, {%8,%9}, {%0,%1,%2,%3};"
        : "+f"(d[0]), "+f"(d[1]), "+f"(d[2]), "+f"(d[3])
        : "r"(a[0]), "r"(a[1]), "r"(a[2]), "r"(a[3]), "r"(b0), "r"(b1));
}
__device__ __forceinline__ void cp_async16(uint32_t saddr, const void* gaddr)
{
    asm volatile("cp.async.cg.shared.global [%0], [%1], 16;"
                 :: "r"(saddr), "l"(gaddr));
}

// ---------------------------------------------------------------------------
// Kernel PRE: p[n] = dot(emb_i[n], u) + fp16 copy of emb_i (2 nodes/warp).
// ---------------------------------------------------------------------------
__global__ __launch_bounds__(256) void pre_kernel(
    const float* __restrict__ emb_i, const float* __restrict__ u, int N)
{
    const int wid  = threadIdx.x >> 5;
    const int lane = threadIdx.x & 31;
    const int n0 = (blockIdx.x * 8 + wid) * 2;
    if (n0 >= N) return;
    const int n1 = n0 + 1;
    const bool has1 = (n1 < N);

    float4 uu = *reinterpret_cast<const float4*>(u + lane * 4);
    float4 v0 = *reinterpret_cast<const float4*>(emb_i + (size_t)n0 * EMB + lane * 4);
    float4 v1 = has1
        ? *reinterpret_cast<const float4*>(emb_i + (size_t)n1 * EMB + lane * 4)
        : make_float4(0.f, 0.f, 0.f, 0.f);

    {
        __half2 a0 = __float22half2_rn(make_float2(v0.x, v0.y));
        __half2 a1 = __float22half2_rn(make_float2(v0.z, v0.w));
        uint2 hw;
        hw.x = *reinterpret_cast<uint32_t*>(&a0);
        hw.y = *reinterpret_cast<uint32_t*>(&a1);
        *reinterpret_cast<uint2*>(&g_emb_h[(size_t)n0 * EMB + lane * 4]) = hw;
    }
    if (has1) {
        __half2 a0 = __float22half2_rn(make_float2(v1.x, v1.y));
        __half2 a1 = __float22half2_rn(make_float2(v1.z, v1.w));
        uint2 hw;
        hw.x = *reinterpret_cast<uint32_t*>(&a0);
        hw.y = *reinterpret_cast<uint32_t*>(&a1);
        *reinterpret_cast<uint2*>(&g_emb_h[(size_t)n1 * EMB + lane * 4]) = hw;
    }

    float s0 = v0.x * uu.x + v0.y * uu.y + v0.z * uu.z + v0.w * uu.w;
    float s1 = v1.x * uu.x + v1.y * uu.y + v1.z * uu.z + v1.w * uu.w;
#pragma unroll
    for (int off = 16; off > 0; off >>= 1) {
        s0 += __shfl_xor_sync(0xffffffffu, s0, off);
        s1 += __shfl_xor_sync(0xffffffffu, s1, off);
    }
    if (lane == 0) {
        g_p[n0] = s0;
        if (has1) g_p[n1] = s1;
    }
}

// ---------------------------------------------------------------------------
// Kernel B: blocks [0, nblk_f): fused softmax + aggregate (warp per feature,
//           16B gather lanes, 2 neighbors/iter).
//           blocks [nblk_f, ..): emb_f fp32 -> fp16 conversion (overlapped).
// ---------------------------------------------------------------------------
__global__ __launch_bounds__(256) void agg_kernel(
    const int* __restrict__ adj, const float* __restrict__ emb_f,
    int F, int nblk_f)
{
    if (blockIdx.x >= (unsigned)nblk_f) {
        int id = (blockIdx.x - nblk_f) * 256 + threadIdx.x;   // float4 index
        size_t base = (size_t)id * 4;
        if (base >= (size_t)F * EMB) return;
        float4 v = *reinterpret_cast<const float4*>(emb_f + base);
        __half2 h0 = __float22half2_rn(make_float2(v.x, v.y));
        __half2 h1 = __float22half2_rn(make_float2(v.z, v.w));
        uint2 hw;
        hw.x = *reinterpret_cast<uint32_t*>(&h0);
        hw.y = *reinterpret_cast<uint32_t*>(&h1);
        *reinterpret_cast<uint2*>(&g_embf_h[base]) = hw;
        return;
    }

    const int f    = blockIdx.x * 8 + (threadIdx.x >> 5);
    const int lane = threadIdx.x & 31;
    if (f >= F) return;

    int   idx = adj[(size_t)f * KNBR + lane];
    float a = g_p[idx] + (idx != 0 ? 0.0f : -10000.0f);
    float m = a;
#pragma unroll
    for (int off = 16; off > 0; off >>= 1)
        m = fmaxf(m, __shfl_xor_sync(0xffffffffu, m, off));
    float e = __expf(a - m);
    float sum = e;
#pragma unroll
    for (int off = 16; off > 0; off >>= 1)
        sum += __shfl_xor_sync(0xffffffffu, sum, off);
    float al = e / sum;

    const int half = lane >> 4;        // 0: even neighbors, 1: odd
    const int li   = lane & 15;        // element group: e = li*8 .. li*8+7

    const uint4* base = reinterpret_cast<const uint4*>(g_emb_h);
    float acc[8];
#pragma unroll
    for (int j = 0; j < 8; j++) acc[j] = 0.0f;

#pragma unroll 8
    for (int ki = 0; ki < KNBR / 2; ki++) {
        int src  = 2 * ki + half;
        int row  = __shfl_sync(0xffffffffu, idx, src);
        float ak = __shfl_sync(0xffffffffu, al,  src);
        uint4 hv = __ldg(base + (size_t)((unsigned)row) * (EMB / 8) + li);
        float2 v0 = __half22float2(*reinterpret_cast<__half2*>(&hv.x));
        float2 v1 = __half22float2(*reinterpret_cast<__half2*>(&hv.y));
        float2 v2 = __half22float2(*reinterpret_cast<__half2*>(&hv.z));
        float2 v3 = __half22float2(*reinterpret_cast<__half2*>(&hv.w));
        acc[0] = fmaf(ak, v0.x, acc[0]);
        acc[1] = fmaf(ak, v0.y, acc[1]);
        acc[2] = fmaf(ak, v1.x, acc[2]);
        acc[3] = fmaf(ak, v1.y, acc[3]);
        acc[4] = fmaf(ak, v2.x, acc[4]);
        acc[5] = fmaf(ak, v2.y, acc[5]);
        acc[6] = fmaf(ak, v3.x, acc[6]);
        acc[7] = fmaf(ak, v3.y, acc[7]);
    }

#pragma unroll
    for (int j = 0; j < 8; j++)
        acc[j] += __shfl_xor_sync(0xffffffffu, acc[j], 16);

    if (half == 0) {
        __half2 o0 = __float22half2_rn(make_float2(acc[0], acc[1]));
        __half2 o1 = __float22half2_rn(make_float2(acc[2], acc[3]));
        __half2 o2 = __float22half2_rn(make_float2(acc[4], acc[5]));
        __half2 o3 = __float22half2_rn(make_float2(acc[6], acc[7]));
        uint4 ow;
        ow.x = *reinterpret_cast<uint32_t*>(&o0);
        ow.y = *reinterpret_cast<uint32_t*>(&o1);
        ow.z = *reinterpret_cast<uint32_t*>(&o2);
        ow.w = *reinterpret_cast<uint32_t*>(&o3);
        *reinterpret_cast<uint4*>(&g_aggh[(size_t)f * EMB + li * 8]) = ow;
    }
}

// ---------------------------------------------------------------------------
// Kernel C: tensor-core gate+fuse, persistent, 2 CTAs/SM, TM=32 tiles with
// TRUE double buffering: tile t+1's cp.async overlaps tile t's MMA+epilogue.
// s_w [n][k] direct copy; B via non-trans ldmatrix. 8 warps = 2f x 4n,
// warp tile 16f x 32n; K=256 in 16 steps.
// ---------------------------------------------------------------------------
#define TM 32
#define WK_LD   264                      // halves per n-row (256 + 8 pad)
#define CAT_LDH 264                      // halves per f-row (256 + 8 pad)
#define S_W_HALFS    (128 * WK_LD)       // 67584 B
#define S_CAT_HALFS  (TM * CAT_LDH)      // 8448 halves = 16896 B
#define S_CAT_BYTES  (S_CAT_HALFS * 2)
#define SMEM_GATE_B  (S_W_HALFS * 2 + 2 * S_CAT_BYTES)   // 101376 B

__global__ __launch_bounds__(256, 2) void gate_fuse_kernel(
    const float* __restrict__ W,      // [128, 256] row-major (n=e, k=j)
    const float* __restrict__ bias,   // [128]
    float* __restrict__ out,          // [F, 128]
    int F)
{
    extern __shared__ __half hsmem[];
    __half* s_w   = hsmem;                 // [n=0..127][k=0..255] (+pad)
    __half* s_cat = hsmem + S_W_HALFS;     // 2 x [f=0..31][k=0..255] (+pad)

    const int t    = threadIdx.x;
    const int lane = t & 31;
    const int wid  = t >> 5;
    const int f0   = (wid >> 2) * 16;      // 0 or 16
    const int nb   = (wid & 3) * 32;       // 0,32,64,96
    const int ntiles = (F + TM - 1) / TM;

    const uint32_t s_cat_u = (uint32_t)__cvta_generic_to_shared(s_cat);
    const uint32_t s_w_u   = (uint32_t)__cvta_generic_to_shared(s_w);

    // prefetch one 32-row cat tile into buffer buf (1024 chunks of 16B)
    auto prefetch = [&](int tile, int buf) {
        int fbase = tile * TM;
#pragma unroll
        for (int r = 0; r < 4; r++) {
            int id  = t + 256 * r;
            int row = id >> 5;               // 0..31
            int c   = id & 31;               // chunk 0..31
            int gf  = fbase + row; if (gf >= F) gf = F - 1;
            const __half* src = (c < 16)
                ? (g_embf_h + (size_t)gf * EMB + c * 8)
                : (g_aggh   + (size_t)gf * EMB + (c - 16) * 8);
            cp_async16(s_cat_u + (uint32_t)buf * S_CAT_BYTES +
                       (uint32_t)((row * CAT_LDH + c * 8) * 2), src);
        }
    };

    // tile0 prefetch flies under the W load/convert
    const int tile0 = blockIdx.x;
    if (tile0 < ntiles) prefetch(tile0, 0);
    asm volatile("cp.async.commit_group;");

    // ---- W -> fp16 smem [n][k], direct vectorized copy (once per block) ----
#pragma unroll
    for (int r = 0; r < 32; r++) {
        int id = t + 256 * r;             // 8192 float4 = 128n x 64 k-quads
        int n  = id >> 6;
        int kq = id & 63;
        float4 v = *reinterpret_cast<const float4*>(W + n * 256 + kq * 4);
        __half2 h0 = __float22half2_rn(make_float2(v.x, v.y));
        __half2 h1 = __float22half2_rn(make_float2(v.z, v.w));
        uint2 hw;
        hw.x = *reinterpret_cast<uint32_t*>(&h0);
        hw.y = *reinterpret_cast<uint32_t*>(&h1);
        *reinterpret_cast<uint2*>(&s_w[n * WK_LD + kq * 4]) = hw;
    }

    // ldmatrix lane addresses
    uint32_t a_addr[2];
#pragma unroll
    for (int b = 0; b < 2; b++)
        a_addr[b] = s_cat_u + (uint32_t)b * S_CAT_BYTES +
            (uint32_t)(((f0 + (lane & 15)) * CAT_LDH + (lane >> 4) * 8) * 2);
    const uint32_t b_lane_addr = s_w_u +
        (uint32_t)((((nb + (lane >> 4) * 8 + (lane & 7)) * WK_LD)
                    + ((lane >> 3) & 1) * 8) * 2);

    int buf = 0;
#pragma unroll 1
    for (int tile = tile0; tile < ntiles; tile += gridDim.x, buf ^= 1) {
        __syncthreads();   // all warps done with buf^1 (2 iters ago) + W ready

        // prefetch next tile into the other buffer (overlaps this tile's MMA)
        int nt = tile + gridDim.x;
        if (nt < ntiles) prefetch(nt, buf ^ 1);
        asm volatile("cp.async.commit_group;");
        asm volatile("cp.async.wait_group 1;" ::: "memory");   // current ready
        __syncthreads();

        // ---- MMA mainloop over K=256 (warp tile 16f x 32n) ----
        float acc[16];
#pragma unroll
        for (int i = 0; i < 16; i++) acc[i] = 0.0f;

#pragma unroll
        for (int ks = 0; ks < 16; ks++) {
            const int k0 = ks * 16;
            uint32_t a[4];
            ldsm_x4(a[0], a[1], a[2], a[3], a_addr[buf] + (uint32_t)(k0 * 2));
#pragma unroll
            for (int np = 0; np < 2; np++) {
                uint32_t b0, b1, b2, b3;
                ldsm_x4(b0, b1, b2, b3,
                        b_lane_addr + (uint32_t)((np * 16 * WK_LD + k0) * 2));
                mma16816(&acc[(np * 2 + 0) * 4], a, b0, b1);
                mma16816(&acc[(np * 2 + 1) * 4], a, b2, b3);
            }
        }

        // ---- Epilogue: ef/agg fp16 from s_cat[buf] ----
        const int fbase = tile * TM;
        const __half* cb = s_cat + buf * S_CAT_HALFS;
        const int r  = lane >> 2;
        const int cq = (lane & 3) * 2;
#pragma unroll
        for (int ti = 0; ti < 4; ti++) {
            int c = nb + ti * 8 + cq;
            float2 b2v = *reinterpret_cast<const float2*>(bias + c);
#pragma unroll
            for (int h = 0; h < 2; h++) {
                int frow = f0 + r + 8 * h;
                int f = fbase + frow;
                if (f >= F) continue;
                float x0 = acc[ti * 4 + 2 * h]     + b2v.x;
                float x1 = acc[ti * 4 + 2 * h + 1] + b2v.y;
                float g0 = 1.0f / (1.0f + __expf(-x0));
                float g1 = 1.0f / (1.0f + __expf(-x1));
                float2 ef = __half22float2(
                    *reinterpret_cast<const __half2*>(&cb[frow * CAT_LDH + c]));
                float2 ag = __half22float2(
                    *reinterpret_cast<const __half2*>(&cb[frow * CAT_LDH + 128 + c]));
                float2 o;
                o.x = g0 * ef.x + (1.0f - g0) * ag.x;
                o.y = g1 * ef.y + (1.0f - g1) * ag.y;
                *reinterpret_cast<float2*>(out + (size_t)f * EMB + c) = o;
            }
        }
    }
}

// ---------------------------------------------------------------------------
extern "C" void kernel_launch(void* const* d_in, const int* in_sizes, int n_in,
                              void* d_out, int out_size)
{
    const int*   adj   = (const int*)d_in[0];     // [F,32]
    const float* emb_i = (const float*)d_in[1];   // [N,128]
    const float* emb_f = (const float*)d_in[2];   // [F,128]
    const float* u     = (const float*)d_in[3];   // [128]
    const float* W     = (const float*)d_in[4];   // [128,256]
    const float* bias  = (const float*)d_in[5];   // [128]
    float*       out   = (float*)d_out;           // [F,128]

    const int F = in_sizes[0] / KNBR;
    const int N = in_sizes[1] / EMB;

    int nsm = 148;
    cudaDeviceGetAttribute(&nsm, cudaDevAttrMultiProcessorCount, 0);

    cudaFuncSetAttribute(gate_fuse_kernel,
                         cudaFuncAttributeMaxDynamicSharedMemorySize, SMEM_GATE_B);

    // pre: 16 nodes per block (2 per warp)
    int nblk_pre = (((N + 1) / 2) + 7) / 8;
    pre_kernel<<<nblk_pre, 256>>>(emb_i, u, N);

    // agg: gather blocks + embf-conversion blocks (independent, overlapped)
    int nblk_f = (F + 7) / 8;
    int nblk_c = (int)(((size_t)F * EMB / 4 + 255) / 256);
    agg_kernel<<<nblk_f + nblk_c, 256>>>(adj, emb_f, F, nblk_f);

    int ntiles = (F + TM - 1) / TM;
    int nblk = 2 * nsm;
    if (nblk > ntiles) nblk = ntiles;
    gate_fuse_kernel<<<nblk, 256, SMEM_GATE_B>>>(W, bias, out, F);
}

// round 17
// speedup vs baseline: 1.9559x; 1.0067x over previous
#include <cuda_runtime.h>
#include <cuda_fp16.h>
#include <cstdint>

// Problem constants: F=50000, K=32, E=128, N_NODE=100000
#define KNBR 32
#define EMB  128
#define MAXF 50000
#define MAXN 100000

// Scratch (no cudaMalloc allowed)
__device__ float g_p[MAXN];                                // 0.4 MB
__device__ alignas(16) __half g_emb_h [MAXN * EMB];        // 25.6 MB
__device__ alignas(16) __half g_embf_h[MAXF * EMB];        // 12.8 MB
__device__ alignas(16) __half g_aggh  [MAXF * EMB];        // 12.8 MB

// ---------------------------------------------------------------------------
// PTX helpers
// ---------------------------------------------------------------------------
__device__ __forceinline__ void ldsm_x4(uint32_t& r0, uint32_t& r1,
                                        uint32_t& r2, uint32_t& r3, uint32_t a)
{
    asm volatile("ldmatrix.sync.aligned.m8n8.x4.shared.b16 {%0,%1,%2,%3}, [%4];"
                 : "=r"(r0), "=r"(r1), "=r"(r2), "=r"(r3) : "r"(a));
}
__device__ __forceinline__ void mma16816(float* d, const uint32_t* a,
                                         uint32_t b0, uint32_t b1)
{
    asm volatile(
        "mma.sync.aligned.m16n8k16.row.col.f32.f16.f16.f32 "
        "{%0,%1,%2,%3}, {%4,%5,%6,%7}, {%8,%9}, {%0,%1,%2,%3};"
        : "+f"(d[0]), "+f"(d[1]), "+f"(d[2]), "+f"(d[3])
        : "r"(a[0]), "r"(a[1]), "r"(a[2]), "r"(a[3]), "r"(b0), "r"(b1));
}
__device__ __forceinline__ void cp_async16(uint32_t saddr, const void* gaddr)
{
    asm volatile("cp.async.cg.shared.global [%0], [%1], 16;"
                 :: "r"(saddr), "l"(gaddr));
}

// ---------------------------------------------------------------------------
// Kernel PRE: p[n] = dot(emb_i[n], u) + fp16 copy of emb_i.
// 4 nodes per warp (4 independent LDG.128 chains -> 4x MLP).
// ---------------------------------------------------------------------------
__global__ __launch_bounds__(256) void pre_kernel(
    const float* __restrict__ emb_i, const float* __restrict__ u, int N)
{
    const int wid  = threadIdx.x >> 5;
    const int lane = threadIdx.x & 31;
    const int nb   = (blockIdx.x * 8 + wid) * 4;
    if (nb >= N) return;

    float4 uu = *reinterpret_cast<const float4*>(u + lane * 4);

    float4 v[4];
    bool   has[4];
#pragma unroll
    for (int j = 0; j < 4; j++) {
        has[j] = (nb + j) < N;
        v[j] = has[j]
            ? *reinterpret_cast<const float4*>(emb_i + (size_t)(nb + j) * EMB + lane * 4)
            : make_float4(0.f, 0.f, 0.f, 0.f);
    }

    // fp16 copies
#pragma unroll
    for (int j = 0; j < 4; j++) {
        if (!has[j]) continue;
        __half2 a0 = __float22half2_rn(make_float2(v[j].x, v[j].y));
        __half2 a1 = __float22half2_rn(make_float2(v[j].z, v[j].w));
        uint2 hw;
        hw.x = *reinterpret_cast<uint32_t*>(&a0);
        hw.y = *reinterpret_cast<uint32_t*>(&a1);
        *reinterpret_cast<uint2*>(&g_emb_h[(size_t)(nb + j) * EMB + lane * 4]) = hw;
    }

    float s[4];
#pragma unroll
    for (int j = 0; j < 4; j++)
        s[j] = v[j].x * uu.x + v[j].y * uu.y + v[j].z * uu.z + v[j].w * uu.w;
#pragma unroll
    for (int off = 16; off > 0; off >>= 1) {
#pragma unroll
        for (int j = 0; j < 4; j++)
            s[j] += __shfl_xor_sync(0xffffffffu, s[j], off);
    }
    if (lane == 0) {
#pragma unroll
        for (int j = 0; j < 4; j++)
            if (has[j]) g_p[nb + j] = s[j];
    }
}

// ---------------------------------------------------------------------------
// Kernel B: blocks [0, nblk_f): fused softmax + aggregate (warp per feature,
//           16B gather lanes, 2 neighbors/iter).
//           blocks [nblk_f, ..): emb_f fp32 -> fp16 conversion (overlapped).
// ---------------------------------------------------------------------------
__global__ __launch_bounds__(256) void agg_kernel(
    const int* __restrict__ adj, const float* __restrict__ emb_f,
    int F, int nblk_f)
{
    if (blockIdx.x >= (unsigned)nblk_f) {
        int id = (blockIdx.x - nblk_f) * 256 + threadIdx.x;   // float4 index
        size_t base = (size_t)id * 4;
        if (base >= (size_t)F * EMB) return;
        float4 v = *reinterpret_cast<const float4*>(emb_f + base);
        __half2 h0 = __float22half2_rn(make_float2(v.x, v.y));
        __half2 h1 = __float22half2_rn(make_float2(v.z, v.w));
        uint2 hw;
        hw.x = *reinterpret_cast<uint32_t*>(&h0);
        hw.y = *reinterpret_cast<uint32_t*>(&h1);
        *reinterpret_cast<uint2*>(&g_embf_h[base]) = hw;
        return;
    }

    const int f    = blockIdx.x * 8 + (threadIdx.x >> 5);
    const int lane = threadIdx.x & 31;
    if (f >= F) return;

    int   idx = adj[(size_t)f * KNBR + lane];
    float a = g_p[idx] + (idx != 0 ? 0.0f : -10000.0f);
    float m = a;
#pragma unroll
    for (int off = 16; off > 0; off >>= 1)
        m = fmaxf(m, __shfl_xor_sync(0xffffffffu, m, off));
    float e = __expf(a - m);
    float sum = e;
#pragma unroll
    for (int off = 16; off > 0; off >>= 1)
        sum += __shfl_xor_sync(0xffffffffu, sum, off);
    float al = e / sum;

    const int half = lane >> 4;        // 0: even neighbors, 1: odd
    const int li   = lane & 15;        // element group: e = li*8 .. li*8+7

    const uint4* base = reinterpret_cast<const uint4*>(g_emb_h);
    float acc[8];
#pragma unroll
    for (int j = 0; j < 8; j++) acc[j] = 0.0f;

#pragma unroll 8
    for (int ki = 0; ki < KNBR / 2; ki++) {
        int src  = 2 * ki + half;
        int row  = __shfl_sync(0xffffffffu, idx, src);
        float ak = __shfl_sync(0xffffffffu, al,  src);
        uint4 hv = __ldg(base + (size_t)((unsigned)row) * (EMB / 8) + li);
        float2 v0 = __half22float2(*reinterpret_cast<__half2*>(&hv.x));
        float2 v1 = __half22float2(*reinterpret_cast<__half2*>(&hv.y));
        float2 v2 = __half22float2(*reinterpret_cast<__half2*>(&hv.z));
        float2 v3 = __half22float2(*reinterpret_cast<__half2*>(&hv.w));
        acc[0] = fmaf(ak, v0.x, acc[0]);
        acc[1] = fmaf(ak, v0.y, acc[1]);
        acc[2] = fmaf(ak, v1.x, acc[2]);
        acc[3] = fmaf(ak, v1.y, acc[3]);
        acc[4] = fmaf(ak, v2.x, acc[4]);
        acc[5] = fmaf(ak, v2.y, acc[5]);
        acc[6] = fmaf(ak, v3.x, acc[6]);
        acc[7] = fmaf(ak, v3.y, acc[7]);
    }

#pragma unroll
    for (int j = 0; j < 8; j++)
        acc[j] += __shfl_xor_sync(0xffffffffu, acc[j], 16);

    if (half == 0) {
        __half2 o0 = __float22half2_rn(make_float2(acc[0], acc[1]));
        __half2 o1 = __float22half2_rn(make_float2(acc[2], acc[3]));
        __half2 o2 = __float22half2_rn(make_float2(acc[4], acc[5]));
        __half2 o3 = __float22half2_rn(make_float2(acc[6], acc[7]));
        uint4 ow;
        ow.x = *reinterpret_cast<uint32_t*>(&o0);
        ow.y = *reinterpret_cast<uint32_t*>(&o1);
        ow.z = *reinterpret_cast<uint32_t*>(&o2);
        ow.w = *reinterpret_cast<uint32_t*>(&o3);
        *reinterpret_cast<uint4*>(&g_aggh[(size_t)f * EMB + li * 8]) = ow;
    }
}

// ---------------------------------------------------------------------------
// Kernel C: tensor-core gate+fuse, persistent, 2 CTAs/SM (R12 config).
// s_w stored [n][k] (direct vectorized copy of W); B via non-trans ldmatrix.
// Full cat tile (emb_f fp16 | agg fp16) via cp.async; tile0's prefetch is
// issued BEFORE the W load so it flies under the conversion.
// Epilogue reads ef/agg fp16 from s_cat; writes out fp32.
// 256 thr = 8 warps (4f x 2e); warp tile 16f x 64e; K=256 in 16 steps.
// ---------------------------------------------------------------------------
#define TM 64
#define WK_LD   264                      // halves per n-row (256 + 8 pad)
#define CAT_LDH 264                      // halves per f-row (256 + 8 pad)
#define S_W_HALFS    (128 * WK_LD)       // 67584 B
#define S_CAT_HALFS  (TM * CAT_LDH)      // 33792 B
#define SMEM_GATE_B  ((S_W_HALFS + S_CAT_HALFS) * 2)     // 101376 B

__global__ __launch_bounds__(256, 2) void gate_fuse_kernel(
    const float* __restrict__ W,      // [128, 256] row-major (n=e, k=j)
    const float* __restrict__ bias,   // [128]
    float* __restrict__ out,          // [F, 128]
    int F)
{
    extern __shared__ __half hsmem[];
    __half* s_w   = hsmem;                 // [n=0..127][k=0..255] (+pad)
    __half* s_cat = hsmem + S_W_HALFS;     // [f=0..63][k=0..255] (+pad)

    const int t    = threadIdx.x;
    const int lane = t & 31;
    const int wid  = t >> 5;
    const int f0   = (wid >> 1) * 16;
    const int nb   = (wid & 1) * 64;
    const int ntiles = (F + TM - 1) / TM;

    const uint32_t s_cat_u = (uint32_t)__cvta_generic_to_shared(s_cat);
    const uint32_t s_w_u   = (uint32_t)__cvta_generic_to_shared(s_w);

    // prefetch one 64-row cat tile (2048 chunks of 16B)
    auto prefetch = [&](int tile) {
        int fbase = tile * TM;
#pragma unroll
        for (int r = 0; r < 8; r++) {
            int id  = t + 256 * r;
            int row = id >> 5;               // 0..63
            int c   = id & 31;               // chunk 0..31
            int gf  = fbase + row; if (gf >= F) gf = F - 1;
            const __half* src = (c < 16)
                ? (g_embf_h + (size_t)gf * EMB + c * 8)
                : (g_aggh   + (size_t)gf * EMB + (c - 16) * 8);
            cp_async16(s_cat_u + (uint32_t)((row * CAT_LDH + c * 8) * 2), src);
        }
    };

    // tile0 prefetch rides under the W load/convert
    const int tile0 = blockIdx.x;
    if (tile0 < ntiles) prefetch(tile0);
    asm volatile("cp.async.commit_group;");

    // ---- W -> fp16 smem [n][k], direct vectorized copy (once per block) ----
#pragma unroll
    for (int r = 0; r < 32; r++) {
        int id = t + 256 * r;             // 8192 float4 = 128n x 64 k-quads
        int n  = id >> 6;
        int kq = id & 63;
        float4 v = *reinterpret_cast<const float4*>(W + n * 256 + kq * 4);
        __half2 h0 = __float22half2_rn(make_float2(v.x, v.y));
        __half2 h1 = __float22half2_rn(make_float2(v.z, v.w));
        uint2 hw;
        hw.x = *reinterpret_cast<uint32_t*>(&h0);
        hw.y = *reinterpret_cast<uint32_t*>(&h1);
        *reinterpret_cast<uint2*>(&s_w[n * WK_LD + kq * 4]) = hw;
    }

    const uint32_t a_lane_addr = s_cat_u +
        (uint32_t)(((f0 + (lane & 15)) * CAT_LDH + (lane >> 4) * 8) * 2);
    const uint32_t b_lane_addr = s_w_u +
        (uint32_t)((((nb + (lane >> 4) * 8 + (lane & 7)) * WK_LD)
                    + ((lane >> 3) & 1) * 8) * 2);

#pragma unroll 1
    for (int tile = tile0; tile < ntiles; tile += gridDim.x) {
        __syncthreads();    // prior epilogue done with s_cat; W stores done (iter 0)

        if (tile != tile0) {
            prefetch(tile);
            asm volatile("cp.async.commit_group;");
        }
        asm volatile("cp.async.wait_group 0;" ::: "memory");
        __syncthreads();    // s_cat fully built, W visible

        // ---- MMA mainloop over K=256 ----
        float acc[32];
#pragma unroll
        for (int i = 0; i < 32; i++) acc[i] = 0.0f;

#pragma unroll
        for (int ks = 0; ks < 16; ks++) {
            const int k0 = ks * 16;
            uint32_t a[4];
            ldsm_x4(a[0], a[1], a[2], a[3], a_lane_addr + (uint32_t)(k0 * 2));
#pragma unroll
            for (int np = 0; np < 4; np++) {
                uint32_t b0, b1, b2, b3;
                ldsm_x4(b0, b1, b2, b3,
                        b_lane_addr + (uint32_t)((np * 16 * WK_LD + k0) * 2));
                mma16816(&acc[(np * 2 + 0) * 4], a, b0, b1);
                mma16816(&acc[(np * 2 + 1) * 4], a, b2, b3);
            }
        }

        // ---- Epilogue: ef/agg fp16 from s_cat ----
        const int fbase = tile * TM;
        const int r  = lane >> 2;
        const int cq = (lane & 3) * 2;
#pragma unroll
        for (int ti = 0; ti < 8; ti++) {
            int c = nb + ti * 8 + cq;
            float2 b2v = *reinterpret_cast<const float2*>(bias + c);
#pragma unroll
            for (int h = 0; h < 2; h++) {
                int frow = f0 + r + 8 * h;
                int f = fbase + frow;
                if (f >= F) continue;
                float x0 = acc[ti * 4 + 2 * h]     + b2v.x;
                float x1 = acc[ti * 4 + 2 * h + 1] + b2v.y;
                float g0 = 1.0f / (1.0f + __expf(-x0));
                float g1 = 1.0f / (1.0f + __expf(-x1));
                float2 ef = __half22float2(
                    *reinterpret_cast<const __half2*>(&s_cat[frow * CAT_LDH + c]));
                float2 ag = __half22float2(
                    *reinterpret_cast<const __half2*>(&s_cat[frow * CAT_LDH + 128 + c]));
                float2 o;
                o.x = g0 * ef.x + (1.0f - g0) * ag.x;
                o.y = g1 * ef.y + (1.0f - g1) * ag.y;
                *reinterpret_cast<float2*>(out + (size_t)f * EMB + c) = o;
            }
        }
    }
}

// ---------------------------------------------------------------------------
extern "C" void kernel_launch(void* const* d_in, const int* in_sizes, int n_in,
                              void* d_out, int out_size)
{
    const int*   adj   = (const int*)d_in[0];     // [F,32]
    const float* emb_i = (const float*)d_in[1];   // [N,128]
    const float* emb_f = (const float*)d_in[2];   // [F,128]
    const float* u     = (const float*)d_in[3];   // [128]
    const float* W     = (const float*)d_in[4];   // [128,256]
    const float* bias  = (const float*)d_in[5];   // [128]
    float*       out   = (float*)d_out;           // [F,128]

    const int F = in_sizes[0] / KNBR;
    const int N = in_sizes[1] / EMB;

    int nsm = 148;
    cudaDeviceGetAttribute(&nsm, cudaDevAttrMultiProcessorCount, 0);

    cudaFuncSetAttribute(gate_fuse_kernel,
                         cudaFuncAttributeMaxDynamicSharedMemorySize, SMEM_GATE_B);

    // pre: 32 nodes per block (4 per warp)
    int nblk_pre = (N + 31) / 32;
    pre_kernel<<<nblk_pre, 256>>>(emb_i, u, N);

    // agg: gather blocks + embf-conversion blocks (independent, overlapped)
    int nblk_f = (F + 7) / 8;
    int nblk_c = (int)(((size_t)F * EMB / 4 + 255) / 256);
    agg_kernel<<<nblk_f + nblk_c, 256>>>(adj, emb_f, F, nblk_f);

    int ntiles = (F + TM - 1) / TM;
    int nblk = 2 * nsm;
    if (nblk > ntiles) nblk = ntiles;
    gate_fuse_kernel<<<nblk, 256, SMEM_GATE_B>>>(W, bias, out, F);
}